// round 1
// baseline (speedup 1.0000x reference)
#include <cuda_runtime.h>

// DenselyCnnAttLayer: out[b,s,d] = sum_l softmax_m( sum_l' s[b,s,l'] * Ws[s,l',m] )[l] * x_l[b,s,d]
// where s[b,s,l] = sum_d x_l[b,s,d].
//
// Shapes: B=64, S=512, L=6, D=512, all fp32.
// Strategy: one CTA per (b,s) row. 128 threads, each holds one float4 from each
// of the 6 layers (24 regs of payload). Single pass over global memory:
//   1) vector loads x_j -> registers, per-thread partial sums
//   2) warp shuffle + cross-warp smem reduce -> per-layer sums (6 floats)
//   3) every thread redundantly computes the 6x6 projection (Ws[s] from smem)
//      and softmax (36 FMA + 6 exp -- trivial)
//   4) weighted combine of the 6 register float4s, one coalesced store.
// Total HBM traffic = 6 reads + 1 write of [B,S,D] = ~470 MB (roofline ~67us).

#define DD   512
#define LL   6
#define NTHR 128   // DD/4 float4 lanes

__global__ __launch_bounds__(NTHR, 8)
void dense_att_kernel(const float* __restrict__ x0,
                      const float* __restrict__ x1,
                      const float* __restrict__ x2,
                      const float* __restrict__ x3,
                      const float* __restrict__ x4,
                      const float* __restrict__ x5,
                      const float* __restrict__ Ws,   // [S, L, L]
                      float* __restrict__ out,        // [B, S, D]
                      int S)
{
    const int row = blockIdx.x;          // b*S + s
    const int s   = row & (S - 1);       // S is a power of two (512)
    const int tid = threadIdx.x;

    __shared__ float sW[LL * LL];        // Ws[s] tile
    __shared__ float ssum[NTHR / 32][LL];

    // Stage Ws[s] into smem (threads 0..35), overlapped with the x loads below.
    if (tid < LL * LL) {
        sW[tid] = Ws[(size_t)s * (LL * LL) + tid];
    }

    const size_t base = (size_t)row * DD + (size_t)tid * 4;

    float4 v[LL];
    float  p[LL];
    {
        const float* xs[LL] = {x0, x1, x2, x3, x4, x5};
#pragma unroll
        for (int j = 0; j < LL; j++) {
            v[j] = *reinterpret_cast<const float4*>(xs[j] + base);
            p[j] = (v[j].x + v[j].y) + (v[j].z + v[j].w);
        }
    }

    // Warp-level reduction of the 6 per-layer partial sums.
#pragma unroll
    for (int off = 16; off > 0; off >>= 1) {
#pragma unroll
        for (int j = 0; j < LL; j++) {
            p[j] += __shfl_xor_sync(0xffffffffu, p[j], off);
        }
    }

    const int warp = tid >> 5;
    const int lane = tid & 31;
    if (lane == 0) {
#pragma unroll
        for (int j = 0; j < LL; j++) ssum[warp][j] = p[j];
    }
    __syncthreads();

    // Every thread finalizes the 6 sums and the tiny softmax redundantly
    // (avoids a second barrier + broadcast).
    float lsum[LL];
#pragma unroll
    for (int j = 0; j < LL; j++) {
        lsum[j] = (ssum[0][j] + ssum[1][j]) + (ssum[2][j] + ssum[3][j]);
    }

    // logits[m] = sum_l lsum[l] * Ws[s, l, m]
    float logit[LL];
#pragma unroll
    for (int m = 0; m < LL; m++) logit[m] = 0.0f;
#pragma unroll
    for (int l = 0; l < LL; l++) {
        const float sl = lsum[l];
#pragma unroll
        for (int m = 0; m < LL; m++) {
            logit[m] = fmaf(sl, sW[l * LL + m], logit[m]);
        }
    }

    // softmax over m
    float mx = logit[0];
#pragma unroll
    for (int m = 1; m < LL; m++) mx = fmaxf(mx, logit[m]);
    float a[LL];
    float den = 0.0f;
#pragma unroll
    for (int m = 0; m < LL; m++) {
        a[m] = __expf(logit[m] - mx);
        den += a[m];
    }
    const float inv = __frcp_rn(den);
#pragma unroll
    for (int m = 0; m < LL; m++) a[m] *= inv;

    // Weighted combine over layers, one coalesced float4 store.
    float4 o;
    o.x = o.y = o.z = o.w = 0.0f;
#pragma unroll
    for (int j = 0; j < LL; j++) {
        o.x = fmaf(a[j], v[j].x, o.x);
        o.y = fmaf(a[j], v[j].y, o.y);
        o.z = fmaf(a[j], v[j].z, o.z);
        o.w = fmaf(a[j], v[j].w, o.w);
    }
    *reinterpret_cast<float4*>(out + base) = o;
}

extern "C" void kernel_launch(void* const* d_in, const int* in_sizes, int n_in,
                              void* d_out, int out_size)
{
    const float* x0 = (const float*)d_in[0];
    const float* x1 = (const float*)d_in[1];
    const float* x2 = (const float*)d_in[2];
    const float* x3 = (const float*)d_in[3];
    const float* x4 = (const float*)d_in[4];
    const float* x5 = (const float*)d_in[5];
    const float* Ws = (const float*)d_in[6];
    float* out = (float*)d_out;

    const int rows = in_sizes[0] / DD;          // B*S
    const int S    = in_sizes[6] / (LL * LL);   // 512

    dense_att_kernel<<<rows, NTHR>>>(x0, x1, x2, x3, x4, x5, Ws, out, S);
}